// round 6
// baseline (speedup 1.0000x reference)
#include <cuda_runtime.h>
#include <cuda_fp16.h>
#include <math_constants.h>

#define NE 100000
#define NR 1000
#define EC 1000000
#define HID 128
#define OUTD 256
#define N2 (2 * NE)
#define SCAN_B 1024
#define SCAN_NB ((N2 + SCAN_B - 1) / SCAN_B)   // 196
#define RT 4                                    // relations per MLP block
#define GNB (NE / 8)                            // node-blocks per chunk (12500)
#define GCH 4                                   // column chunks of 64

// ---- scratch (device globals: allocation-free) ----
__device__ float  g_eh[NE];
__device__ float  g_et[NE];
__device__ float  g_er[NR];
__device__ __half g_tWh[NR * OUTD];
__device__ __half g_tWt[NR * OUTD];
__device__ int    g_hist[N2];
__device__ int    g_off[N2];
__device__ int    g_cur[N2];
__device__ float2 g_pk[2 * EC];        // per-slot packed (alpha, rel-bits)
__device__ int    g_part[SCAN_NB];
__device__ int    g_partoff[SCAN_NB];

// ---- zero histograms ----
__global__ void k_zero_hist() {
    int i = blockIdx.x * blockDim.x + threadIdx.x;
    if (i < N2) g_hist[i] = 0;
}

// ---- per-entity attention scores: warp per node ----
__global__ void k_node_scores(const float* __restrict__ xe,
                              const float* __restrict__ wah,
                              const float* __restrict__ wat) {
    int warp = (blockIdx.x * blockDim.x + threadIdx.x) >> 5;
    int lane = threadIdx.x & 31;
    if (warp >= NE) return;
    const float4* row = (const float4*)(xe + (size_t)warp * HID);
    float4 v = row[lane];
    float4 a = ((const float4*)wah)[lane];
    float4 b = ((const float4*)wat)[lane];
    float sh = v.x * a.x + v.y * a.y + v.z * a.z + v.w * a.w;
    float st = v.x * b.x + v.y * b.y + v.z * b.z + v.w * b.w;
    #pragma unroll
    for (int o = 16; o; o >>= 1) {
        sh += __shfl_xor_sync(0xFFFFFFFFu, sh, o);
        st += __shfl_xor_sync(0xFFFFFFFFu, st, o);
    }
    if (lane == 0) { g_eh[warp] = sh; g_et[warp] = st; }
}

// ---- per-relation attention scores: warp per relation ----
__global__ void k_rel_scores(const float* __restrict__ xr,
                             const float* __restrict__ war) {
    int warp = (blockIdx.x * blockDim.x + threadIdx.x) >> 5;
    int lane = threadIdx.x & 31;
    if (warp >= NR) return;
    const float4* row = (const float4*)(xr + (size_t)warp * HID);
    float4 v = row[lane];
    float4 a = ((const float4*)war)[lane];
    float s = v.x * a.x + v.y * a.y + v.z * a.z + v.w * a.w;
    #pragma unroll
    for (int o = 16; o; o >>= 1) s += __shfl_xor_sync(0xFFFFFFFFu, s, o);
    if (lane == 0) g_er[warp] = s;
}

// ---- fused relation MLP + W_r fold: 4 relations per block (250 blocks) ----
__global__ void k_mlp(const float* __restrict__ xr,
                      const float* __restrict__ W1, const float* __restrict__ b1,
                      const float* __restrict__ W2, const float* __restrict__ b2,
                      const float* __restrict__ Wr) {
    __shared__ float xs[RT][HID];
    __shared__ float hs[RT][2 * HID];
    int r0 = blockIdx.x * RT;
    int tid = threadIdx.x;

    for (int i = tid; i < RT * HID; i += 256) {
        int rr = i >> 7, c = i & 127;
        xs[rr][c] = xr[(size_t)(r0 + rr) * HID + c];
    }
    __syncthreads();

    {
        float acc[RT];
        float bb = b1[tid];
        #pragma unroll
        for (int i = 0; i < RT; i++) acc[i] = bb;
        for (int k = 0; k < HID; k += 4) {
            float w0 = W1[(k + 0) * 256 + tid];
            float w1 = W1[(k + 1) * 256 + tid];
            float w2 = W1[(k + 2) * 256 + tid];
            float w3 = W1[(k + 3) * 256 + tid];
            #pragma unroll
            for (int i = 0; i < RT; i++)
                acc[i] += xs[i][k] * w0 + xs[i][k + 1] * w1
                        + xs[i][k + 2] * w2 + xs[i][k + 3] * w3;
        }
        #pragma unroll
        for (int i = 0; i < RT; i++) hs[i][tid] = acc[i];
    }
    __syncthreads();

    {
        int c = tid & 127;
        int g = tid >> 7;
        float acc[RT / 2];
        #pragma unroll
        for (int i = 0; i < RT / 2; i++) acc[i] = 0.0f;
        for (int j = 0; j < 2 * HID; j += 4) {
            float w0 = W2[(j + 0) * HID + c];
            float w1 = W2[(j + 1) * HID + c];
            float w2 = W2[(j + 2) * HID + c];
            float w3 = W2[(j + 3) * HID + c];
            #pragma unroll
            for (int i = 0; i < RT / 2; i++)
                acc[i] += hs[g * (RT / 2) + i][j] * w0 + hs[g * (RT / 2) + i][j + 1] * w1
                        + hs[g * (RT / 2) + i][j + 2] * w2 + hs[g * (RT / 2) + i][j + 3] * w3;
        }
        float bb = b2[c];
        #pragma unroll
        for (int i = 0; i < RT / 2; i++) xs[g * (RT / 2) + i][c] += bb + acc[i];
    }
    __syncthreads();

    {
        float ah[RT], at[RT];
        #pragma unroll
        for (int i = 0; i < RT; i++) { ah[i] = 0.0f; at[i] = 0.0f; }
        for (int k = 0; k < HID; k += 2) {
            float wh0 = Wr[(k + 0) * 256 + tid];
            float wh1 = Wr[(k + 1) * 256 + tid];
            float wt0 = Wr[(k + HID + 0) * 256 + tid];
            float wt1 = Wr[(k + HID + 1) * 256 + tid];
            #pragma unroll
            for (int i = 0; i < RT; i++) {
                float m0 = xs[i][k], m1 = xs[i][k + 1];
                ah[i] += m0 * wh0 + m1 * wh1;
                at[i] += m0 * wt0 + m1 * wt1;
            }
        }
        #pragma unroll
        for (int i = 0; i < RT; i++) {
            g_tWh[(size_t)(r0 + i) * OUTD + tid] = __float2half(ah[i]);
            g_tWt[(size_t)(r0 + i) * OUTD + tid] = __float2half(at[i]);
        }
    }
}

// ---- degree histogram ----
__global__ void k_hist(const int* __restrict__ ei) {
    int e = blockIdx.x * blockDim.x + threadIdx.x;
    if (e >= EC) return;
    atomicAdd(&g_hist[ei[e]], 1);
    atomicAdd(&g_hist[NE + ei[EC + e]], 1);
}

// ---- scan stage 1 ----
__global__ void k_scan1() {
    __shared__ int sh[SCAN_B];
    int t = threadIdx.x;
    int i = blockIdx.x * SCAN_B + t;
    int v = (i < N2) ? g_hist[i] : 0;
    sh[t] = v;
    __syncthreads();
    #pragma unroll
    for (int d = 1; d < SCAN_B; d <<= 1) {
        int x = (t >= d) ? sh[t - d] : 0;
        __syncthreads();
        sh[t] += x;
        __syncthreads();
    }
    if (i < N2) g_off[i] = sh[t] - v;
    if (t == SCAN_B - 1) g_part[blockIdx.x] = sh[t];
}

// ---- scan stage 2 ----
__global__ void k_scan2() {
    if (threadIdx.x == 0) {
        int run = 0;
        for (int b = 0; b < SCAN_NB; b++) {
            g_partoff[b] = run;
            run += g_part[b];
        }
    }
}

// ---- scan stage 3 ----
__global__ void k_scan3() {
    int i = blockIdx.x * blockDim.x + threadIdx.x;
    if (i < N2) {
        int o = g_off[i] + g_partoff[i / SCAN_B];
        g_off[i] = o;
        g_cur[i] = o;
    }
}

// ---- fused CSR fill + logits ----
__global__ void k_fill(const int* __restrict__ ei, const int* __restrict__ rel) {
    int e = blockIdx.x * blockDim.x + threadIdx.x;
    if (e >= EC) return;
    int h = ei[e], t = ei[EC + e], r = rel[e];
    float er = g_er[r];
    float rbits = __int_as_float(r);
    float lh = g_eh[h] + er;
    lh = lh > 0.0f ? lh : 0.01f * lh;
    float lt = g_et[t] + er;
    lt = lt > 0.0f ? lt : 0.01f * lt;
    int p = atomicAdd(&g_cur[h], 1);
    g_pk[p] = make_float2(lh, rbits);
    int q = atomicAdd(&g_cur[NE + t], 1);
    g_pk[q] = make_float2(lt, rbits);
}

// ---- softmax in place: pk.x logit -> alpha ----
__global__ void k_alpha() {
    int n = (blockIdx.x * blockDim.x + threadIdx.x) >> 5;
    int lane = threadIdx.x & 31;
    if (n >= NE) return;
    #pragma unroll
    for (int d = 0; d < 2; d++) {
        int base = g_off[d * NE + n];
        int deg  = g_hist[d * NE + n];
        if (deg <= 0) continue;
        if (deg <= 32) {
            float l = -CUDART_INF_F;
            float rb = 0.0f;
            if (lane < deg) {
                float2 pk = g_pk[base + lane];
                l = pk.x; rb = pk.y;
            }
            float m = l;
            #pragma unroll
            for (int o = 16; o; o >>= 1) m = fmaxf(m, __shfl_xor_sync(0xFFFFFFFFu, m, o));
            float z = (lane < deg) ? __expf(l - m) : 0.0f;
            float s = z;
            #pragma unroll
            for (int o = 16; o; o >>= 1) s += __shfl_xor_sync(0xFFFFFFFFu, s, o);
            float inv = 1.0f / (s + 1e-16f);
            if (lane < deg) g_pk[base + lane] = make_float2(z * inv, rb);
        } else {
            float m = -CUDART_INF_F;
            for (int j = lane; j < deg; j += 32) m = fmaxf(m, g_pk[base + j].x);
            #pragma unroll
            for (int o = 16; o; o >>= 1) m = fmaxf(m, __shfl_xor_sync(0xFFFFFFFFu, m, o));
            float s = 0.0f;
            for (int j = lane; j < deg; j += 32) s += __expf(g_pk[base + j].x - m);
            #pragma unroll
            for (int o = 16; o; o >>= 1) s += __shfl_xor_sync(0xFFFFFFFFu, s, o);
            float inv = 1.0f / (s + 1e-16f);
            for (int j = lane; j < deg; j += 32) {
                float2 pk = g_pk[base + j];
                g_pk[base + j] = make_float2(__expf(pk.x - m) * inv, pk.y);
            }
        }
    }
}

// ---- column-chunked gather: chunk of 64 cols, both dirs, L1-resident tables ----
// grid.x = GCH * GNB, chunk-major so co-resident CTAs share table working set.
__device__ __forceinline__ void chunk_accum(int base, int deg, int co,
                                            const __half2* __restrict__ tb,
                                            float& ax, float& ay) {
    int j = 0;
    for (; j + 4 <= deg; j += 4) {
        float2 p0 = g_pk[base + j + 0];
        float2 p1 = g_pk[base + j + 1];
        float2 p2 = g_pk[base + j + 2];
        float2 p3 = g_pk[base + j + 3];
        __half2 t0 = tb[__float_as_int(p0.y) * 128 + co];
        __half2 t1 = tb[__float_as_int(p1.y) * 128 + co];
        __half2 t2 = tb[__float_as_int(p2.y) * 128 + co];
        __half2 t3 = tb[__float_as_int(p3.y) * 128 + co];
        float2 f0 = __half22float2(t0);
        float2 f1 = __half22float2(t1);
        float2 f2 = __half22float2(t2);
        float2 f3 = __half22float2(t3);
        ax += p0.x * f0.x + p1.x * f1.x + p2.x * f2.x + p3.x * f3.x;
        ay += p0.x * f0.y + p1.x * f1.y + p2.x * f2.y + p3.x * f3.y;
    }
    for (; j < deg; j++) {
        float2 p = g_pk[base + j];
        float2 f = __half22float2(tb[__float_as_int(p.y) * 128 + co]);
        ax += p.x * f.x;
        ay += p.x * f.y;
    }
}

__global__ void k_gather(const float* __restrict__ br, float* __restrict__ out) {
    int chunk = blockIdx.x / GNB;
    int nb    = blockIdx.x % GNB;
    int wid   = threadIdx.x >> 5;
    int lane  = threadIdx.x & 31;
    int n     = nb * 8 + wid;
    int co    = chunk * 32 + lane;          // half2 offset within a 128-half2 row

    float ax = 0.0f, ay = 0.0f;
    chunk_accum(g_off[n],      g_hist[n],      co, (const __half2*)g_tWh, ax, ay);
    chunk_accum(g_off[NE + n], g_hist[NE + n], co, (const __half2*)g_tWt, ax, ay);

    float2 bb = ((const float2*)br)[co];
    ((float2*)out)[(size_t)n * 128 + co] = make_float2(ax + bb.x, ay + bb.y);
}

extern "C" void kernel_launch(void* const* d_in, const int* in_sizes, int n_in,
                              void* d_out, int out_size) {
    const float* x_e  = (const float*)d_in[0];
    const float* x_r  = (const float*)d_in[1];
    const int*   ei   = (const int*)d_in[2];
    const int*   rel  = (const int*)d_in[3];
    const float* w_ah = (const float*)d_in[5];
    const float* w_at = (const float*)d_in[6];
    const float* w_ar = (const float*)d_in[7];
    const float* W1   = (const float*)d_in[8];
    const float* b1   = (const float*)d_in[9];
    const float* W2   = (const float*)d_in[10];
    const float* b2   = (const float*)d_in[11];
    const float* Wr   = (const float*)d_in[12];
    const float* br   = (const float*)d_in[13];
    float* out = (float*)d_out;

    k_zero_hist<<<(N2 + 255) / 256, 256>>>();
    k_node_scores<<<(NE + 7) / 8, 256>>>(x_e, w_ah, w_at);
    k_rel_scores<<<(NR + 7) / 8, 256>>>(x_r, w_ar);
    k_hist<<<(EC + 255) / 256, 256>>>(ei);
    k_mlp<<<NR / RT, 256>>>(x_r, W1, b1, W2, b2, Wr);
    k_scan1<<<SCAN_NB, SCAN_B>>>();
    k_scan2<<<1, 32>>>();
    k_scan3<<<(N2 + 255) / 256, 256>>>();
    k_fill<<<(EC + 255) / 256, 256>>>(ei, rel);
    k_alpha<<<(NE + 7) / 8, 256>>>();
    k_gather<<<GCH * GNB, 256>>>(br, out);
}

// round 7
// speedup vs baseline: 1.2277x; 1.2277x over previous
#include <cuda_runtime.h>
#include <cuda_fp16.h>
#include <math_constants.h>

#define NE 100000
#define NR 1000
#define EC 1000000
#define HID 128
#define OUTD 256
#define N2 (2 * NE)
#define SCAN_B 1024
#define SCAN_NB ((N2 + SCAN_B - 1) / SCAN_B)   // 196
#define RT 4                                    // relations per MLP block

// ---- scratch (device globals: allocation-free) ----
__device__ float  g_eh[NE];
__device__ float  g_et[NE];
__device__ float  g_er[NR];
__device__ float  g_lh[EC];
__device__ float  g_lt[EC];
__device__ __half g_tWh[NR * OUTD];
__device__ __half g_tWt[NR * OUTD];
__device__ int    g_hist[N2];
__device__ int    g_off[N2];
__device__ int    g_cur[N2];
__device__ int    g_idx[2 * EC];
__device__ int    g_part[SCAN_NB];
__device__ int    g_partoff[SCAN_NB];

// ---- zero histograms ----
__global__ void k_zero_hist() {
    int i = blockIdx.x * blockDim.x + threadIdx.x;
    if (i < N2) g_hist[i] = 0;
}

// ---- per-entity attention scores: warp per node ----
__global__ void k_node_scores(const float* __restrict__ xe,
                              const float* __restrict__ wah,
                              const float* __restrict__ wat) {
    int warp = (blockIdx.x * blockDim.x + threadIdx.x) >> 5;
    int lane = threadIdx.x & 31;
    if (warp >= NE) return;
    const float4* row = (const float4*)(xe + (size_t)warp * HID);
    float4 v = row[lane];
    float4 a = ((const float4*)wah)[lane];
    float4 b = ((const float4*)wat)[lane];
    float sh = v.x * a.x + v.y * a.y + v.z * a.z + v.w * a.w;
    float st = v.x * b.x + v.y * b.y + v.z * b.z + v.w * b.w;
    #pragma unroll
    for (int o = 16; o; o >>= 1) {
        sh += __shfl_xor_sync(0xFFFFFFFFu, sh, o);
        st += __shfl_xor_sync(0xFFFFFFFFu, st, o);
    }
    if (lane == 0) { g_eh[warp] = sh; g_et[warp] = st; }
}

// ---- per-relation attention scores: warp per relation ----
__global__ void k_rel_scores(const float* __restrict__ xr,
                             const float* __restrict__ war) {
    int warp = (blockIdx.x * blockDim.x + threadIdx.x) >> 5;
    int lane = threadIdx.x & 31;
    if (warp >= NR) return;
    const float4* row = (const float4*)(xr + (size_t)warp * HID);
    float4 v = row[lane];
    float4 a = ((const float4*)war)[lane];
    float s = v.x * a.x + v.y * a.y + v.z * a.z + v.w * a.w;
    #pragma unroll
    for (int o = 16; o; o >>= 1) s += __shfl_xor_sync(0xFFFFFFFFu, s, o);
    if (lane == 0) g_er[warp] = s;
}

// ---- fused relation MLP + W_r fold: 4 relations per block (250 blocks), x4 unroll ----
__global__ void k_mlp(const float* __restrict__ xr,
                      const float* __restrict__ W1, const float* __restrict__ b1,
                      const float* __restrict__ W2, const float* __restrict__ b2,
                      const float* __restrict__ Wr) {
    __shared__ float xs[RT][HID];        // x_r rows, later msg rows
    __shared__ float hs[RT][2 * HID];    // hidden layer
    int r0 = blockIdx.x * RT;
    int tid = threadIdx.x;               // 256 threads

    for (int i = tid; i < RT * HID; i += 256) {
        int rr = i >> 7, c = i & 127;
        xs[rr][c] = xr[(size_t)(r0 + rr) * HID + c];
    }
    __syncthreads();

    // layer 1: hs[i][tid] = b1[tid] + sum_k xs[i][k] * W1[k*256+tid]
    {
        float acc[RT];
        float bb = b1[tid];
        #pragma unroll
        for (int i = 0; i < RT; i++) acc[i] = bb;
        for (int k = 0; k < HID; k += 4) {
            float w0 = W1[(k + 0) * 256 + tid];
            float w1 = W1[(k + 1) * 256 + tid];
            float w2 = W1[(k + 2) * 256 + tid];
            float w3 = W1[(k + 3) * 256 + tid];
            #pragma unroll
            for (int i = 0; i < RT; i++)
                acc[i] += xs[i][k] * w0 + xs[i][k + 1] * w1
                        + xs[i][k + 2] * w2 + xs[i][k + 3] * w3;
        }
        #pragma unroll
        for (int i = 0; i < RT; i++) hs[i][tid] = acc[i];
    }
    __syncthreads();

    // layer 2 + residual: xs[i][c] += b2[c] + sum_j hs[i][j] * W2[j*128+c]
    {
        int c = tid & 127;
        int g = tid >> 7;                  // 0/1: each half handles RT/2 relations
        float acc[RT / 2];
        #pragma unroll
        for (int i = 0; i < RT / 2; i++) acc[i] = 0.0f;
        for (int j = 0; j < 2 * HID; j += 4) {
            float w0 = W2[(j + 0) * HID + c];
            float w1 = W2[(j + 1) * HID + c];
            float w2 = W2[(j + 2) * HID + c];
            float w3 = W2[(j + 3) * HID + c];
            #pragma unroll
            for (int i = 0; i < RT / 2; i++)
                acc[i] += hs[g * (RT / 2) + i][j] * w0 + hs[g * (RT / 2) + i][j + 1] * w1
                        + hs[g * (RT / 2) + i][j + 2] * w2 + hs[g * (RT / 2) + i][j + 3] * w3;
        }
        float bb = b2[c];
        #pragma unroll
        for (int i = 0; i < RT / 2; i++) xs[g * (RT / 2) + i][c] += bb + acc[i];
    }
    __syncthreads();

    // layer 3: tables. ah[i] = sum_k msg[i][k]*Wr[k*256+tid]; at with k+128
    {
        float ah[RT], at[RT];
        #pragma unroll
        for (int i = 0; i < RT; i++) { ah[i] = 0.0f; at[i] = 0.0f; }
        for (int k = 0; k < HID; k += 2) {
            float wh0 = Wr[(k + 0) * 256 + tid];
            float wh1 = Wr[(k + 1) * 256 + tid];
            float wt0 = Wr[(k + HID + 0) * 256 + tid];
            float wt1 = Wr[(k + HID + 1) * 256 + tid];
            #pragma unroll
            for (int i = 0; i < RT; i++) {
                float m0 = xs[i][k], m1 = xs[i][k + 1];
                ah[i] += m0 * wh0 + m1 * wh1;
                at[i] += m0 * wt0 + m1 * wt1;
            }
        }
        #pragma unroll
        for (int i = 0; i < RT; i++) {
            g_tWh[(size_t)(r0 + i) * OUTD + tid] = __float2half(ah[i]);
            g_tWt[(size_t)(r0 + i) * OUTD + tid] = __float2half(at[i]);
        }
    }
}

// ---- edge pass: logits + degree histogram ----
__global__ void k_logits(const int* __restrict__ ei, const int* __restrict__ rel) {
    int e = blockIdx.x * blockDim.x + threadIdx.x;
    if (e >= EC) return;
    int h = ei[e], t = ei[EC + e], r = rel[e];
    float er = g_er[r];
    float lh = g_eh[h] + er;
    lh = lh > 0.0f ? lh : 0.01f * lh;
    float lt = g_et[t] + er;
    lt = lt > 0.0f ? lt : 0.01f * lt;
    g_lh[e] = lh;
    g_lt[e] = lt;
    atomicAdd(&g_hist[h], 1);
    atomicAdd(&g_hist[NE + t], 1);
}

// ---- scan stage 1 ----
__global__ void k_scan1() {
    __shared__ int sh[SCAN_B];
    int t = threadIdx.x;
    int i = blockIdx.x * SCAN_B + t;
    int v = (i < N2) ? g_hist[i] : 0;
    sh[t] = v;
    __syncthreads();
    #pragma unroll
    for (int d = 1; d < SCAN_B; d <<= 1) {
        int x = (t >= d) ? sh[t - d] : 0;
        __syncthreads();
        sh[t] += x;
        __syncthreads();
    }
    if (i < N2) g_off[i] = sh[t] - v;
    if (t == SCAN_B - 1) g_part[blockIdx.x] = sh[t];
}

// ---- scan stage 2 ----
__global__ void k_scan2() {
    if (threadIdx.x == 0) {
        int run = 0;
        for (int b = 0; b < SCAN_NB; b++) {
            g_partoff[b] = run;
            run += g_part[b];
        }
    }
}

// ---- scan stage 3 ----
__global__ void k_scan3() {
    int i = blockIdx.x * blockDim.x + threadIdx.x;
    if (i < N2) {
        int o = g_off[i] + g_partoff[i / SCAN_B];
        g_off[i] = o;
        g_cur[i] = o;
    }
}

// ---- CSR fill ----
__global__ void k_fill(const int* __restrict__ ei) {
    int e = blockIdx.x * blockDim.x + threadIdx.x;
    if (e >= EC) return;
    int h = ei[e], t = ei[EC + e];
    int p = atomicAdd(&g_cur[h], 1);
    g_idx[p] = e;
    int q = atomicAdd(&g_cur[NE + t], 1);
    g_idx[q] = e;
}

// ---- fma 8 halfs into fp32 accumulators ----
__device__ __forceinline__ void fma8(float* acc, uint4 p, float a) {
    __half2* h = reinterpret_cast<__half2*>(&p);
    #pragma unroll
    for (int q = 0; q < 4; q++) {
        float2 f = __half22float2(h[q]);
        acc[2 * q]     += a * f.x;
        acc[2 * q + 1] += a * f.y;
    }
}

// ---- segment softmax + weighted half-table accumulation ----
__device__ __forceinline__ void seg_accum(int base, int deg, int lane,
                                          const float* __restrict__ lg,
                                          const int* __restrict__ rel,
                                          const __half* __restrict__ table,
                                          float* acc) {
    if (deg <= 0) return;
    if (deg <= 32) {
        float l = -CUDART_INF_F;
        int r = 0;
        if (lane < deg) {
            int e = g_idx[base + lane];
            l = lg[e];
            r = rel[e];
        }
        float m = l;
        #pragma unroll
        for (int o = 16; o; o >>= 1) m = fmaxf(m, __shfl_xor_sync(0xFFFFFFFFu, m, o));
        float z = (lane < deg) ? __expf(l - m) : 0.0f;
        float s = z;
        #pragma unroll
        for (int o = 16; o; o >>= 1) s += __shfl_xor_sync(0xFFFFFFFFu, s, o);
        float a_own = z / (s + 1e-16f);
        for (int j = 0; j < deg; j++) {
            float a = __shfl_sync(0xFFFFFFFFu, a_own, j);
            int rj  = __shfl_sync(0xFFFFFFFFu, r, j);
            uint4 p = ((const uint4*)(table + (size_t)rj * OUTD))[lane];
            fma8(acc, p, a);
        }
    } else {
        float m = -CUDART_INF_F;
        for (int j = lane; j < deg; j += 32) m = fmaxf(m, lg[g_idx[base + j]]);
        #pragma unroll
        for (int o = 16; o; o >>= 1) m = fmaxf(m, __shfl_xor_sync(0xFFFFFFFFu, m, o));
        float s = 0.0f;
        for (int j = lane; j < deg; j += 32) s += __expf(lg[g_idx[base + j]] - m);
        #pragma unroll
        for (int o = 16; o; o >>= 1) s += __shfl_xor_sync(0xFFFFFFFFu, s, o);
        float inv = 1.0f / (s + 1e-16f);
        for (int c0 = 0; c0 < deg; c0 += 32) {
            int j = c0 + lane;
            float a_own = 0.0f;
            int r = 0;
            if (j < deg) {
                int e = g_idx[base + j];
                a_own = __expf(lg[e] - m) * inv;
                r = rel[e];
            }
            int cnt = min(32, deg - c0);
            for (int jj = 0; jj < cnt; jj++) {
                float a = __shfl_sync(0xFFFFFFFFu, a_own, jj);
                int rj  = __shfl_sync(0xFFFFFFFFu, r, jj);
                uint4 p = ((const uint4*)(table + (size_t)rj * OUTD))[lane];
                fma8(acc, p, a);
            }
        }
    }
}

// ---- gather: one warp per node, both directions, single row store ----
__global__ void k_gather(const int* __restrict__ rel,
                         const float* __restrict__ br,
                         float* __restrict__ out) {
    int n = (blockIdx.x * blockDim.x + threadIdx.x) >> 5;
    int lane = threadIdx.x & 31;
    if (n >= NE) return;

    float acc[8];
    #pragma unroll
    for (int q = 0; q < 8; q++) acc[q] = 0.0f;

    seg_accum(g_off[n],      g_hist[n],      lane, g_lh, rel, g_tWh, acc);
    seg_accum(g_off[NE + n], g_hist[NE + n], lane, g_lt, rel, g_tWt, acc);

    float4 b0 = ((const float4*)(br + lane * 8))[0];
    float4 b1 = ((const float4*)(br + lane * 8))[1];
    float4* o = (float4*)(out + (size_t)n * OUTD + lane * 8);
    o[0] = make_float4(acc[0] + b0.x, acc[1] + b0.y, acc[2] + b0.z, acc[3] + b0.w);
    o[1] = make_float4(acc[4] + b1.x, acc[5] + b1.y, acc[6] + b1.z, acc[7] + b1.w);
}

extern "C" void kernel_launch(void* const* d_in, const int* in_sizes, int n_in,
                              void* d_out, int out_size) {
    const float* x_e  = (const float*)d_in[0];
    const float* x_r  = (const float*)d_in[1];
    const int*   ei   = (const int*)d_in[2];
    const int*   rel  = (const int*)d_in[3];
    const float* w_ah = (const float*)d_in[5];
    const float* w_at = (const float*)d_in[6];
    const float* w_ar = (const float*)d_in[7];
    const float* W1   = (const float*)d_in[8];
    const float* b1   = (const float*)d_in[9];
    const float* W2   = (const float*)d_in[10];
    const float* b2   = (const float*)d_in[11];
    const float* Wr   = (const float*)d_in[12];
    const float* br   = (const float*)d_in[13];
    float* out = (float*)d_out;

    k_zero_hist<<<(N2 + 255) / 256, 256>>>();
    k_node_scores<<<(NE + 7) / 8, 256>>>(x_e, w_ah, w_at);
    k_rel_scores<<<(NR + 7) / 8, 256>>>(x_r, w_ar);
    k_mlp<<<NR / RT, 256>>>(x_r, W1, b1, W2, b2, Wr);
    k_logits<<<(EC + 255) / 256, 256>>>(ei, rel);
    k_scan1<<<SCAN_NB, SCAN_B>>>();
    k_scan2<<<1, 32>>>();
    k_scan3<<<(N2 + 255) / 256, 256>>>();
    k_fill<<<(EC + 255) / 256, 256>>>(ei);
    k_gather<<<(NE + 7) / 8, 256>>>(rel, br, out);
}

// round 8
// speedup vs baseline: 1.3348x; 1.0873x over previous
#include <cuda_runtime.h>
#include <cuda_fp16.h>
#include <math_constants.h>

#define NE 100000
#define NR 1000
#define EC 1000000
#define HID 128
#define OUTD 256
#define N2 (2 * NE)
#define SCAN_B 1024
#define SCAN_NB ((N2 + SCAN_B - 1) / SCAN_B)   // 196
#define RT 8                                    // relations per MLP block (125 blocks = 1 wave)

// ---- scratch (device globals: allocation-free) ----
__device__ float  g_eh[NE];
__device__ float  g_et[NE];
__device__ float  g_er[NR];
__device__ float  g_lh[EC];
__device__ float  g_lt[EC];
__device__ __half g_tWh[NR * OUTD];
__device__ __half g_tWt[NR * OUTD];
__device__ int    g_hist[N2];
__device__ int    g_off[N2];
__device__ int    g_cur[N2];
__device__ int    g_idx[2 * EC];
__device__ int    g_part[SCAN_NB];
__device__ int    g_partoff[SCAN_NB];

// ---- zero histograms ----
__global__ void k_zero_hist() {
    int i = blockIdx.x * blockDim.x + threadIdx.x;
    if (i < N2) g_hist[i] = 0;
}

// ---- per-entity attention scores: warp per node ----
__global__ void k_node_scores(const float* __restrict__ xe,
                              const float* __restrict__ wah,
                              const float* __restrict__ wat) {
    int warp = (blockIdx.x * blockDim.x + threadIdx.x) >> 5;
    int lane = threadIdx.x & 31;
    if (warp >= NE) return;
    const float4* row = (const float4*)(xe + (size_t)warp * HID);
    float4 v = row[lane];
    float4 a = ((const float4*)wah)[lane];
    float4 b = ((const float4*)wat)[lane];
    float sh = v.x * a.x + v.y * a.y + v.z * a.z + v.w * a.w;
    float st = v.x * b.x + v.y * b.y + v.z * b.z + v.w * b.w;
    #pragma unroll
    for (int o = 16; o; o >>= 1) {
        sh += __shfl_xor_sync(0xFFFFFFFFu, sh, o);
        st += __shfl_xor_sync(0xFFFFFFFFu, st, o);
    }
    if (lane == 0) { g_eh[warp] = sh; g_et[warp] = st; }
}

// ---- per-relation attention scores: warp per relation ----
__global__ void k_rel_scores(const float* __restrict__ xr,
                             const float* __restrict__ war) {
    int warp = (blockIdx.x * blockDim.x + threadIdx.x) >> 5;
    int lane = threadIdx.x & 31;
    if (warp >= NR) return;
    const float4* row = (const float4*)(xr + (size_t)warp * HID);
    float4 v = row[lane];
    float4 a = ((const float4*)war)[lane];
    float s = v.x * a.x + v.y * a.y + v.z * a.z + v.w * a.w;
    #pragma unroll
    for (int o = 16; o; o >>= 1) s += __shfl_xor_sync(0xFFFFFFFFu, s, o);
    if (lane == 0) g_er[warp] = s;
}

// ---- fused relation MLP + W_r fold: RT=8 relations/block, LDG.128 weight loads ----
// Thread layouts give each thread 4 adjacent output columns and a k-stride
// subset; cross-group sums go through a 32KB smem reduction buffer.
__global__ __launch_bounds__(256) void k_mlp(
        const float* __restrict__ xr,
        const float* __restrict__ W1, const float* __restrict__ b1,
        const float* __restrict__ W2, const float* __restrict__ b2,
        const float* __restrict__ Wr) {
    __shared__ float xs[RT][HID];        // x_r rows; becomes msg after layer 2
    __shared__ float hs[RT][2 * HID];    // hidden layer
    __shared__ float red[8192];          // 32 KB reduction buffer (reused per layer)
    int r0 = blockIdx.x * RT;
    int tid = threadIdx.x;               // 256 threads

    for (int i = tid; i < RT * HID; i += 256) {
        int rr = i >> 7, c = i & 127;
        xs[rr][c] = xr[(size_t)(r0 + rr) * HID + c];
    }
    __syncthreads();

    // ---- layer 1: hs[i][c] = b1[c] + sum_k xs[i][k] * W1[k*256+c]  (c<256, k<128)
    {
        int kk = tid >> 6;               // k-group 0..3
        int u  = tid & 63;               // cols 4u..4u+3
        float4 acc[RT];
        #pragma unroll
        for (int i = 0; i < RT; i++) acc[i] = make_float4(0.f, 0.f, 0.f, 0.f);
        #pragma unroll 4
        for (int m = 0; m < 32; m++) {
            int k = kk + 4 * m;
            float4 w = *(const float4*)&W1[k * 256 + 4 * u];
            #pragma unroll
            for (int i = 0; i < RT; i++) {
                float x = xs[i][k];
                acc[i].x += x * w.x; acc[i].y += x * w.y;
                acc[i].z += x * w.z; acc[i].w += x * w.w;
            }
        }
        #pragma unroll
        for (int i = 0; i < RT; i++)
            *(float4*)&red[(kk * 8 + i) * 256 + 4 * u] = acc[i];
        __syncthreads();
        #pragma unroll
        for (int p = 0; p < 8; p++) {
            int idx = p * 256 + tid;           // 2048 outputs
            int i = idx >> 8, c = idx & 255;
            hs[i][c] = b1[c] + red[(0 + i) * 256 + c] + red[(8 + i) * 256 + c]
                     + red[(16 + i) * 256 + c] + red[(24 + i) * 256 + c];
        }
        __syncthreads();
    }

    // ---- layer 2 + residual: xs[i][c] += b2[c] + sum_j hs[i][j] * W2[j*128+c]  (c<128, j<256)
    {
        int jj = tid >> 5;               // j-group 0..7
        int u  = tid & 31;               // cols 4u..4u+3
        float4 acc[RT];
        #pragma unroll
        for (int i = 0; i < RT; i++) acc[i] = make_float4(0.f, 0.f, 0.f, 0.f);
        #pragma unroll 4
        for (int m = 0; m < 32; m++) {
            int j = jj + 8 * m;
            float4 w = *(const float4*)&W2[j * 128 + 4 * u];
            #pragma unroll
            for (int i = 0; i < RT; i++) {
                float x = hs[i][j];
                acc[i].x += x * w.x; acc[i].y += x * w.y;
                acc[i].z += x * w.z; acc[i].w += x * w.w;
            }
        }
        #pragma unroll
        for (int i = 0; i < RT; i++)
            *(float4*)&red[(jj * 8 + i) * 128 + 4 * u] = acc[i];
        __syncthreads();
        #pragma unroll
        for (int p = 0; p < 4; p++) {
            int idx = p * 256 + tid;           // 1024 outputs
            int i = idx >> 7, c = idx & 127;
            float v = b2[c];
            #pragma unroll
            for (int g = 0; g < 8; g++) v += red[(g * 8 + i) * 128 + c];
            xs[i][c] += v;                     // msg = x_r + mlp(x_r)
        }
        __syncthreads();
    }

    // ---- layer 3: tables. tWh[i][c] = sum_k msg[i][k]*Wr[k*256+c];
    //               tWt[i][c] with Wr[(k+128)*256+c]  (c<256, k<128)
    {
        int half = tid >> 7;             // 0: h-table, 1: t-table
        int kk   = (tid >> 6) & 1;       // k-group 0,1
        int u    = tid & 63;             // cols 4u..4u+3
        float4 acc[RT];
        #pragma unroll
        for (int i = 0; i < RT; i++) acc[i] = make_float4(0.f, 0.f, 0.f, 0.f);
        #pragma unroll 4
        for (int m = 0; m < 64; m++) {
            int k = kk + 2 * m;
            float4 w = *(const float4*)&Wr[(half * 128 + k) * 256 + 4 * u];
            #pragma unroll
            for (int i = 0; i < RT; i++) {
                float x = xs[i][k];
                acc[i].x += x * w.x; acc[i].y += x * w.y;
                acc[i].z += x * w.z; acc[i].w += x * w.w;
            }
        }
        // red layout: ((kk*2 + half)*8 + i)*256 + c
        #pragma unroll
        for (int i = 0; i < RT; i++)
            *(float4*)&red[((kk * 2 + half) * 8 + i) * 256 + 4 * u] = acc[i];
        __syncthreads();
        #pragma unroll
        for (int p = 0; p < 16; p++) {
            int idx = p * 256 + tid;           // 4096 outputs
            int c = idx & 255;
            int q = idx >> 8;                  // 0..15
            int i = q & 7, hf = q >> 3;
            float v = red[((0 + hf) * 8 + i) * 256 + c]
                    + red[((2 + hf) * 8 + i) * 256 + c];
            if (hf == 0) g_tWh[(size_t)(r0 + i) * OUTD + c] = __float2half(v);
            else         g_tWt[(size_t)(r0 + i) * OUTD + c] = __float2half(v);
        }
    }
}

// ---- edge pass: logits + degree histogram ----
__global__ void k_logits(const int* __restrict__ ei, const int* __restrict__ rel) {
    int e = blockIdx.x * blockDim.x + threadIdx.x;
    if (e >= EC) return;
    int h = ei[e], t = ei[EC + e], r = rel[e];
    float er = g_er[r];
    float lh = g_eh[h] + er;
    lh = lh > 0.0f ? lh : 0.01f * lh;
    float lt = g_et[t] + er;
    lt = lt > 0.0f ? lt : 0.01f * lt;
    g_lh[e] = lh;
    g_lt[e] = lt;
    atomicAdd(&g_hist[h], 1);
    atomicAdd(&g_hist[NE + t], 1);
}

// ---- scan stage 1 ----
__global__ void k_scan1() {
    __shared__ int sh[SCAN_B];
    int t = threadIdx.x;
    int i = blockIdx.x * SCAN_B + t;
    int v = (i < N2) ? g_hist[i] : 0;
    sh[t] = v;
    __syncthreads();
    #pragma unroll
    for (int d = 1; d < SCAN_B; d <<= 1) {
        int x = (t >= d) ? sh[t - d] : 0;
        __syncthreads();
        sh[t] += x;
        __syncthreads();
    }
    if (i < N2) g_off[i] = sh[t] - v;
    if (t == SCAN_B - 1) g_part[blockIdx.x] = sh[t];
}

// ---- scan stage 2 ----
__global__ void k_scan2() {
    if (threadIdx.x == 0) {
        int run = 0;
        for (int b = 0; b < SCAN_NB; b++) {
            g_partoff[b] = run;
            run += g_part[b];
        }
    }
}

// ---- scan stage 3 ----
__global__ void k_scan3() {
    int i = blockIdx.x * blockDim.x + threadIdx.x;
    if (i < N2) {
        int o = g_off[i] + g_partoff[i / SCAN_B];
        g_off[i] = o;
        g_cur[i] = o;
    }
}

// ---- CSR fill ----
__global__ void k_fill(const int* __restrict__ ei) {
    int e = blockIdx.x * blockDim.x + threadIdx.x;
    if (e >= EC) return;
    int h = ei[e], t = ei[EC + e];
    int p = atomicAdd(&g_cur[h], 1);
    g_idx[p] = e;
    int q = atomicAdd(&g_cur[NE + t], 1);
    g_idx[q] = e;
}

// ---- fma 8 halfs into fp32 accumulators ----
__device__ __forceinline__ void fma8(float* acc, uint4 p, float a) {
    __half2* h = reinterpret_cast<__half2*>(&p);
    #pragma unroll
    for (int q = 0; q < 4; q++) {
        float2 f = __half22float2(h[q]);
        acc[2 * q]     += a * f.x;
        acc[2 * q + 1] += a * f.y;
    }
}

// ---- segment softmax + weighted half-table accumulation ----
__device__ __forceinline__ void seg_accum(int base, int deg, int lane,
                                          const float* __restrict__ lg,
                                          const int* __restrict__ rel,
                                          const __half* __restrict__ table,
                                          float* acc) {
    if (deg <= 0) return;
    if (deg <= 32) {
        float l = -CUDART_INF_F;
        int r = 0;
        if (lane < deg) {
            int e = g_idx[base + lane];
            l = lg[e];
            r = rel[e];
        }
        float m = l;
        #pragma unroll
        for (int o = 16; o; o >>= 1) m = fmaxf(m, __shfl_xor_sync(0xFFFFFFFFu, m, o));
        float z = (lane < deg) ? __expf(l - m) : 0.0f;
        float s = z;
        #pragma unroll
        for (int o = 16; o; o >>= 1) s += __shfl_xor_sync(0xFFFFFFFFu, s, o);
        float a_own = z / (s + 1e-16f);
        for (int j = 0; j < deg; j++) {
            float a = __shfl_sync(0xFFFFFFFFu, a_own, j);
            int rj  = __shfl_sync(0xFFFFFFFFu, r, j);
            uint4 p = ((const uint4*)(table + (size_t)rj * OUTD))[lane];
            fma8(acc, p, a);
        }
    } else {
        float m = -CUDART_INF_F;
        for (int j = lane; j < deg; j += 32) m = fmaxf(m, lg[g_idx[base + j]]);
        #pragma unroll
        for (int o = 16; o; o >>= 1) m = fmaxf(m, __shfl_xor_sync(0xFFFFFFFFu, m, o));
        float s = 0.0f;
        for (int j = lane; j < deg; j += 32) s += __expf(lg[g_idx[base + j]] - m);
        #pragma unroll
        for (int o = 16; o; o >>= 1) s += __shfl_xor_sync(0xFFFFFFFFu, s, o);
        float inv = 1.0f / (s + 1e-16f);
        for (int c0 = 0; c0 < deg; c0 += 32) {
            int j = c0 + lane;
            float a_own = 0.0f;
            int r = 0;
            if (j < deg) {
                int e = g_idx[base + j];
                a_own = __expf(lg[e] - m) * inv;
                r = rel[e];
            }
            int cnt = min(32, deg - c0);
            for (int jj = 0; jj < cnt; jj++) {
                float a = __shfl_sync(0xFFFFFFFFu, a_own, jj);
                int rj  = __shfl_sync(0xFFFFFFFFu, r, jj);
                uint4 p = ((const uint4*)(table + (size_t)rj * OUTD))[lane];
                fma8(acc, p, a);
            }
        }
    }
}

// ---- gather: one warp per node, both directions, single row store ----
__global__ void k_gather(const int* __restrict__ rel,
                         const float* __restrict__ br,
                         float* __restrict__ out) {
    int n = (blockIdx.x * blockDim.x + threadIdx.x) >> 5;
    int lane = threadIdx.x & 31;
    if (n >= NE) return;

    float acc[8];
    #pragma unroll
    for (int q = 0; q < 8; q++) acc[q] = 0.0f;

    seg_accum(g_off[n],      g_hist[n],      lane, g_lh, rel, g_tWh, acc);
    seg_accum(g_off[NE + n], g_hist[NE + n], lane, g_lt, rel, g_tWt, acc);

    float4 b0 = ((const float4*)(br + lane * 8))[0];
    float4 b1 = ((const float4*)(br + lane * 8))[1];
    float4* o = (float4*)(out + (size_t)n * OUTD + lane * 8);
    o[0] = make_float4(acc[0] + b0.x, acc[1] + b0.y, acc[2] + b0.z, acc[3] + b0.w);
    o[1] = make_float4(acc[4] + b1.x, acc[5] + b1.y, acc[6] + b1.z, acc[7] + b1.w);
}

extern "C" void kernel_launch(void* const* d_in, const int* in_sizes, int n_in,
                              void* d_out, int out_size) {
    const float* x_e  = (const float*)d_in[0];
    const float* x_r  = (const float*)d_in[1];
    const int*   ei   = (const int*)d_in[2];
    const int*   rel  = (const int*)d_in[3];
    const float* w_ah = (const float*)d_in[5];
    const float* w_at = (const float*)d_in[6];
    const float* w_ar = (const float*)d_in[7];
    const float* W1   = (const float*)d_in[8];
    const float* b1   = (const float*)d_in[9];
    const float* W2   = (const float*)d_in[10];
    const float* b2   = (const float*)d_in[11];
    const float* Wr   = (const float*)d_in[12];
    const float* br   = (const float*)d_in[13];
    float* out = (float*)d_out;

    k_zero_hist<<<(N2 + 255) / 256, 256>>>();
    k_node_scores<<<(NE + 7) / 8, 256>>>(x_e, w_ah, w_at);
    k_rel_scores<<<(NR + 7) / 8, 256>>>(x_r, w_ar);
    k_mlp<<<NR / RT, 256>>>(x_r, W1, b1, W2, b2, Wr);
    k_logits<<<(EC + 255) / 256, 256>>>(ei, rel);
    k_scan1<<<SCAN_NB, SCAN_B>>>();
    k_scan2<<<1, 32>>>();
    k_scan3<<<(N2 + 255) / 256, 256>>>();
    k_fill<<<(EC + 255) / 256, 256>>>(ei);
    k_gather<<<(NE + 7) / 8, 256>>>(rel, br, out);
}

// round 9
// speedup vs baseline: 1.3571x; 1.0167x over previous
#include <cuda_runtime.h>
#include <cuda_fp16.h>
#include <math_constants.h>

#define NE 100000
#define NR 1000
#define EC 1000000
#define HID 128
#define OUTD 256
#define N2 (2 * NE)
#define SCAN_B 1024
#define SCAN_NB ((N2 + SCAN_B - 1) / SCAN_B)   // 196
#define RT 8                                    // relations per MLP block (125 blocks = 1 wave)

// ---- scratch (device globals: allocation-free) ----
__device__ float  g_eh[NE];
__device__ float  g_et[NE];
__device__ float  g_er[NR];
__device__ float  g_lh[EC];
__device__ float  g_lt[EC];
__device__ __half g_tWh[NR * OUTD];
__device__ __half g_tWt[NR * OUTD];
__device__ int    g_hist[N2];
__device__ int    g_off[N2];
__device__ int    g_cur[N2];
__device__ int    g_idx[2 * EC];
__device__ int    g_part[SCAN_NB];
__device__ int    g_partoff[SCAN_NB];

// ---- zero histograms ----
__global__ void k_zero_hist() {
    int i = blockIdx.x * blockDim.x + threadIdx.x;
    if (i < N2) g_hist[i] = 0;
}

// ---- per-entity attention scores: warp per node ----
__global__ void k_node_scores(const float* __restrict__ xe,
                              const float* __restrict__ wah,
                              const float* __restrict__ wat) {
    int warp = (blockIdx.x * blockDim.x + threadIdx.x) >> 5;
    int lane = threadIdx.x & 31;
    if (warp >= NE) return;
    const float4* row = (const float4*)(xe + (size_t)warp * HID);
    float4 v = row[lane];
    float4 a = ((const float4*)wah)[lane];
    float4 b = ((const float4*)wat)[lane];
    float sh = v.x * a.x + v.y * a.y + v.z * a.z + v.w * a.w;
    float st = v.x * b.x + v.y * b.y + v.z * b.z + v.w * b.w;
    #pragma unroll
    for (int o = 16; o; o >>= 1) {
        sh += __shfl_xor_sync(0xFFFFFFFFu, sh, o);
        st += __shfl_xor_sync(0xFFFFFFFFu, st, o);
    }
    if (lane == 0) { g_eh[warp] = sh; g_et[warp] = st; }
}

// ---- per-relation attention scores: warp per relation ----
__global__ void k_rel_scores(const float* __restrict__ xr,
                             const float* __restrict__ war) {
    int warp = (blockIdx.x * blockDim.x + threadIdx.x) >> 5;
    int lane = threadIdx.x & 31;
    if (warp >= NR) return;
    const float4* row = (const float4*)(xr + (size_t)warp * HID);
    float4 v = row[lane];
    float4 a = ((const float4*)war)[lane];
    float s = v.x * a.x + v.y * a.y + v.z * a.z + v.w * a.w;
    #pragma unroll
    for (int o = 16; o; o >>= 1) s += __shfl_xor_sync(0xFFFFFFFFu, s, o);
    if (lane == 0) g_er[warp] = s;
}

// ---- fused relation MLP + W_r fold: RT=8/block, 512 threads, LDG.128 ----
// Each thread owns 4 relations (tid>>8 selects the subset), 4 adjacent output
// columns, and a k-stride subset; cross-group sums via 32KB smem reduction.
__global__ __launch_bounds__(512) void k_mlp(
        const float* __restrict__ xr,
        const float* __restrict__ W1, const float* __restrict__ b1,
        const float* __restrict__ W2, const float* __restrict__ b2,
        const float* __restrict__ Wr) {
    __shared__ float xs[RT][HID];        // x_r rows; becomes msg after layer 2
    __shared__ float hs[RT][2 * HID];    // hidden layer
    __shared__ float red[8192];          // 32 KB reduction buffer (reused per layer)
    int r0 = blockIdx.x * RT;
    int tid = threadIdx.x;               // 512 threads
    int rh  = tid >> 8;                  // relation subset: rels rh*4 .. rh*4+3

    for (int i = tid; i < RT * HID; i += 512) {
        int rr = i >> 7, c = i & 127;
        xs[rr][c] = xr[(size_t)(r0 + rr) * HID + c];
    }
    __syncthreads();

    // ---- layer 1: hs[i][c] = b1[c] + sum_k xs[i][k] * W1[k*256+c]  (c<256, k<128)
    {
        int kk = (tid >> 6) & 3;         // k-group 0..3
        int u  = tid & 63;               // cols 4u..4u+3
        float4 acc[4];
        #pragma unroll
        for (int i = 0; i < 4; i++) acc[i] = make_float4(0.f, 0.f, 0.f, 0.f);
        #pragma unroll 4
        for (int m = 0; m < 32; m++) {
            int k = kk + 4 * m;
            float4 w = *(const float4*)&W1[k * 256 + 4 * u];
            #pragma unroll
            for (int i = 0; i < 4; i++) {
                float x = xs[rh * 4 + i][k];
                acc[i].x += x * w.x; acc[i].y += x * w.y;
                acc[i].z += x * w.z; acc[i].w += x * w.w;
            }
        }
        #pragma unroll
        for (int i = 0; i < 4; i++)
            *(float4*)&red[(kk * 8 + rh * 4 + i) * 256 + 4 * u] = acc[i];
        __syncthreads();
        #pragma unroll
        for (int p = 0; p < 4; p++) {
            int idx = p * 512 + tid;           // 2048 outputs
            int i = idx >> 8, c = idx & 255;
            hs[i][c] = b1[c] + red[(0 + i) * 256 + c] + red[(8 + i) * 256 + c]
                     + red[(16 + i) * 256 + c] + red[(24 + i) * 256 + c];
        }
        __syncthreads();
    }

    // ---- layer 2 + residual: xs[i][c] += b2[c] + sum_j hs[i][j] * W2[j*128+c]  (c<128, j<256)
    {
        int jj = (tid >> 5) & 7;         // j-group 0..7
        int u  = tid & 31;               // cols 4u..4u+3
        float4 acc[4];
        #pragma unroll
        for (int i = 0; i < 4; i++) acc[i] = make_float4(0.f, 0.f, 0.f, 0.f);
        #pragma unroll 4
        for (int m = 0; m < 32; m++) {
            int j = jj + 8 * m;
            float4 w = *(const float4*)&W2[j * 128 + 4 * u];
            #pragma unroll
            for (int i = 0; i < 4; i++) {
                float x = hs[rh * 4 + i][j];
                acc[i].x += x * w.x; acc[i].y += x * w.y;
                acc[i].z += x * w.z; acc[i].w += x * w.w;
            }
        }
        #pragma unroll
        for (int i = 0; i < 4; i++)
            *(float4*)&red[(jj * 8 + rh * 4 + i) * 128 + 4 * u] = acc[i];
        __syncthreads();
        #pragma unroll
        for (int p = 0; p < 2; p++) {
            int idx = p * 512 + tid;           // 1024 outputs
            int i = idx >> 7, c = idx & 127;
            float v = b2[c];
            #pragma unroll
            for (int g = 0; g < 8; g++) v += red[(g * 8 + i) * 128 + c];
            xs[i][c] += v;                     // msg = x_r + mlp(x_r)
        }
        __syncthreads();
    }

    // ---- layer 3: tables. tWh[i][c] = sum_k msg[i][k]*Wr[k*256+c];
    //               tWt[i][c] with Wr[(k+128)*256+c]  (c<256, k<128)
    {
        int half = (tid >> 7) & 1;       // 0: h-table, 1: t-table
        int kk   = (tid >> 6) & 1;       // k-group 0,1
        int u    = tid & 63;             // cols 4u..4u+3
        float4 acc[4];
        #pragma unroll
        for (int i = 0; i < 4; i++) acc[i] = make_float4(0.f, 0.f, 0.f, 0.f);
        #pragma unroll 4
        for (int m = 0; m < 64; m++) {
            int k = kk + 2 * m;
            float4 w = *(const float4*)&Wr[(half * 128 + k) * 256 + 4 * u];
            #pragma unroll
            for (int i = 0; i < 4; i++) {
                float x = xs[rh * 4 + i][k];
                acc[i].x += x * w.x; acc[i].y += x * w.y;
                acc[i].z += x * w.z; acc[i].w += x * w.w;
            }
        }
        // red layout: ((kk*2 + half)*8 + rel)*256 + c
        #pragma unroll
        for (int i = 0; i < 4; i++)
            *(float4*)&red[((kk * 2 + half) * 8 + rh * 4 + i) * 256 + 4 * u] = acc[i];
        __syncthreads();
        #pragma unroll
        for (int p = 0; p < 8; p++) {
            int idx = p * 512 + tid;           // 4096 outputs
            int c = idx & 255;
            int q = idx >> 8;                  // 0..15
            int i = q & 7, hf = q >> 3;
            float v = red[((0 + hf) * 8 + i) * 256 + c]
                    + red[((2 + hf) * 8 + i) * 256 + c];
            if (hf == 0) g_tWh[(size_t)(r0 + i) * OUTD + c] = __float2half(v);
            else         g_tWt[(size_t)(r0 + i) * OUTD + c] = __float2half(v);
        }
    }
}

// ---- edge pass: logits + degree histogram ----
__global__ void k_logits(const int* __restrict__ ei, const int* __restrict__ rel) {
    int e = blockIdx.x * blockDim.x + threadIdx.x;
    if (e >= EC) return;
    int h = ei[e], t = ei[EC + e], r = rel[e];
    float er = g_er[r];
    float lh = g_eh[h] + er;
    lh = lh > 0.0f ? lh : 0.01f * lh;
    float lt = g_et[t] + er;
    lt = lt > 0.0f ? lt : 0.01f * lt;
    g_lh[e] = lh;
    g_lt[e] = lt;
    atomicAdd(&g_hist[h], 1);
    atomicAdd(&g_hist[NE + t], 1);
}

// ---- scan stage 1 ----
__global__ void k_scan1() {
    __shared__ int sh[SCAN_B];
    int t = threadIdx.x;
    int i = blockIdx.x * SCAN_B + t;
    int v = (i < N2) ? g_hist[i] : 0;
    sh[t] = v;
    __syncthreads();
    #pragma unroll
    for (int d = 1; d < SCAN_B; d <<= 1) {
        int x = (t >= d) ? sh[t - d] : 0;
        __syncthreads();
        sh[t] += x;
        __syncthreads();
    }
    if (i < N2) g_off[i] = sh[t] - v;
    if (t == SCAN_B - 1) g_part[blockIdx.x] = sh[t];
}

// ---- scan stage 2 ----
__global__ void k_scan2() {
    if (threadIdx.x == 0) {
        int run = 0;
        for (int b = 0; b < SCAN_NB; b++) {
            g_partoff[b] = run;
            run += g_part[b];
        }
    }
}

// ---- scan stage 3 ----
__global__ void k_scan3() {
    int i = blockIdx.x * blockDim.x + threadIdx.x;
    if (i < N2) {
        int o = g_off[i] + g_partoff[i / SCAN_B];
        g_off[i] = o;
        g_cur[i] = o;
    }
}

// ---- CSR fill ----
__global__ void k_fill(const int* __restrict__ ei) {
    int e = blockIdx.x * blockDim.x + threadIdx.x;
    if (e >= EC) return;
    int h = ei[e], t = ei[EC + e];
    int p = atomicAdd(&g_cur[h], 1);
    g_idx[p] = e;
    int q = atomicAdd(&g_cur[NE + t], 1);
    g_idx[q] = e;
}

// ---- fma 8 halfs into fp32 accumulators ----
__device__ __forceinline__ void fma8(float* acc, uint4 p, float a) {
    __half2* h = reinterpret_cast<__half2*>(&p);
    #pragma unroll
    for (int q = 0; q < 4; q++) {
        float2 f = __half22float2(h[q]);
        acc[2 * q]     += a * f.x;
        acc[2 * q + 1] += a * f.y;
    }
}

// ---- segment softmax + weighted half-table accumulation ----
__device__ __forceinline__ void seg_accum(int base, int deg, int lane,
                                          const float* __restrict__ lg,
                                          const int* __restrict__ rel,
                                          const __half* __restrict__ table,
                                          float* acc) {
    if (deg <= 0) return;
    if (deg <= 32) {
        float l = -CUDART_INF_F;
        int r = 0;
        if (lane < deg) {
            int e = g_idx[base + lane];
            l = lg[e];
            r = rel[e];
        }
        float m = l;
        #pragma unroll
        for (int o = 16; o; o >>= 1) m = fmaxf(m, __shfl_xor_sync(0xFFFFFFFFu, m, o));
        float z = (lane < deg) ? __expf(l - m) : 0.0f;
        float s = z;
        #pragma unroll
        for (int o = 16; o; o >>= 1) s += __shfl_xor_sync(0xFFFFFFFFu, s, o);
        float a_own = z / (s + 1e-16f);
        for (int j = 0; j < deg; j++) {
            float a = __shfl_sync(0xFFFFFFFFu, a_own, j);
            int rj  = __shfl_sync(0xFFFFFFFFu, r, j);
            uint4 p = ((const uint4*)(table + (size_t)rj * OUTD))[lane];
            fma8(acc, p, a);
        }
    } else {
        float m = -CUDART_INF_F;
        for (int j = lane; j < deg; j += 32) m = fmaxf(m, lg[g_idx[base + j]]);
        #pragma unroll
        for (int o = 16; o; o >>= 1) m = fmaxf(m, __shfl_xor_sync(0xFFFFFFFFu, m, o));
        float s = 0.0f;
        for (int j = lane; j < deg; j += 32) s += __expf(lg[g_idx[base + j]] - m);
        #pragma unroll
        for (int o = 16; o; o >>= 1) s += __shfl_xor_sync(0xFFFFFFFFu, s, o);
        float inv = 1.0f / (s + 1e-16f);
        for (int c0 = 0; c0 < deg; c0 += 32) {
            int j = c0 + lane;
            float a_own = 0.0f;
            int r = 0;
            if (j < deg) {
                int e = g_idx[base + j];
                a_own = __expf(lg[e] - m) * inv;
                r = rel[e];
            }
            int cnt = min(32, deg - c0);
            for (int jj = 0; jj < cnt; jj++) {
                float a = __shfl_sync(0xFFFFFFFFu, a_own, jj);
                int rj  = __shfl_sync(0xFFFFFFFFu, r, jj);
                uint4 p = ((const uint4*)(table + (size_t)rj * OUTD))[lane];
                fma8(acc, p, a);
            }
        }
    }
}

// ---- gather: one warp per node, both directions, single row store ----
__global__ void k_gather(const int* __restrict__ rel,
                         const float* __restrict__ br,
                         float* __restrict__ out) {
    int n = (blockIdx.x * blockDim.x + threadIdx.x) >> 5;
    int lane = threadIdx.x & 31;
    if (n >= NE) return;

    float acc[8];
    #pragma unroll
    for (int q = 0; q < 8; q++) acc[q] = 0.0f;

    seg_accum(g_off[n],      g_hist[n],      lane, g_lh, rel, g_tWh, acc);
    seg_accum(g_off[NE + n], g_hist[NE + n], lane, g_lt, rel, g_tWt, acc);

    float4 b0 = ((const float4*)(br + lane * 8))[0];
    float4 b1 = ((const float4*)(br + lane * 8))[1];
    float4* o = (float4*)(out + (size_t)n * OUTD + lane * 8);
    o[0] = make_float4(acc[0] + b0.x, acc[1] + b0.y, acc[2] + b0.z, acc[3] + b0.w);
    o[1] = make_float4(acc[4] + b1.x, acc[5] + b1.y, acc[6] + b1.z, acc[7] + b1.w);
}

extern "C" void kernel_launch(void* const* d_in, const int* in_sizes, int n_in,
                              void* d_out, int out_size) {
    const float* x_e  = (const float*)d_in[0];
    const float* x_r  = (const float*)d_in[1];
    const int*   ei   = (const int*)d_in[2];
    const int*   rel  = (const int*)d_in[3];
    const float* w_ah = (const float*)d_in[5];
    const float* w_at = (const float*)d_in[6];
    const float* w_ar = (const float*)d_in[7];
    const float* W1   = (const float*)d_in[8];
    const float* b1   = (const float*)d_in[9];
    const float* W2   = (const float*)d_in[10];
    const float* b2   = (const float*)d_in[11];
    const float* Wr   = (const float*)d_in[12];
    const float* br   = (const float*)d_in[13];
    float* out = (float*)d_out;

    k_zero_hist<<<(N2 + 255) / 256, 256>>>();
    k_node_scores<<<(NE + 7) / 8, 256>>>(x_e, w_ah, w_at);
    k_rel_scores<<<(NR + 7) / 8, 256>>>(x_r, w_ar);
    k_mlp<<<NR / RT, 512>>>(x_r, W1, b1, W2, b2, Wr);
    k_logits<<<(EC + 255) / 256, 256>>>(ei, rel);
    k_scan1<<<SCAN_NB, SCAN_B>>>();
    k_scan2<<<1, 32>>>();
    k_scan3<<<(N2 + 255) / 256, 256>>>();
    k_fill<<<(EC + 255) / 256, 256>>>(ei);
    k_gather<<<(NE + 7) / 8, 256>>>(rel, br, out);
}